// round 11
// baseline (speedup 1.0000x reference)
#include <cuda_runtime.h>
#include <cuda_bf16.h>
#include <math.h>

#define Ll 4096
#define Dd 64
#define BH 32
#define NBLK 64
#define TSEL 6
#define SCALE 0.125f
#define P68 68

// fragment-major K/V buffers: word index = k8*FK_S8 + nt*FK_SN + (grp*4+tig)*2 + half
#define FK_SN 66
#define FK_S8 532          // 8*FK_SN + 4  (bank-spread padding)
#define FK_WORDS 4256      // per buffer (floats)

typedef unsigned long long ull;

__device__ __forceinline__ ull dup2(float x) {
    ull r; asm("mov.b64 %0, {%1, %1};" : "=l"(r) : "f"(x)); return r;
}
__device__ __forceinline__ void ffma2(ull& d, ull a, ull b) {
    asm("fma.rn.f32x2 %0, %1, %2, %3;" : "=l"(d) : "l"(a), "l"(b), "l"(d));
}
__device__ __forceinline__ float2 unpk(ull v) {
    float2 f; asm("mov.b64 {%0, %1}, %2;" : "=f"(f.x), "=f"(f.y) : "l"(v)); return f;
}
__device__ __forceinline__ unsigned cvt_tf32(float x) {
    unsigned r; asm("cvt.rna.tf32.f32 %0, %1;" : "=r"(r) : "f"(x)); return r;
}
__device__ __forceinline__ void mma_tf32(float* c,
    unsigned a0, unsigned a1, unsigned a2, unsigned a3,
    unsigned b0, unsigned b1) {
    asm volatile(
        "mma.sync.aligned.m16n8k8.row.col.f32.tf32.tf32.f32 "
        "{%0,%1,%2,%3}, {%4,%5,%6,%7}, {%8,%9}, {%0,%1,%2,%3};"
        : "+f"(c[0]), "+f"(c[1]), "+f"(c[2]), "+f"(c[3])
        : "r"(a0), "r"(a1), "r"(a2), "r"(a3), "r"(b0), "r"(b1));
}

__device__ float g_qb[BH * NBLK * Dd];
__device__ float g_kb[BH * NBLK * Dd];
__device__ int   g_lut[BH * NBLK * TSEL];
__device__ float g_kv[(size_t)BH * NBLK * Dd * Dd];
__device__ float g_z[BH * NBLK * Dd];
__device__ float g_kvtot[BH * Dd * Dd];
__device__ float g_ztot[BH * Dd];

#define GSTEP(Abase, Bbase, ACC)                                        \
    {                                                                   \
        float4 af = *(const float4*)(Abase);                            \
        ulonglong2 bp = *(const ulonglong2*)(Bbase);                    \
        ull a0 = dup2(af.x), a1 = dup2(af.y), a2 = dup2(af.z), a3 = dup2(af.w); \
        ffma2(ACC[0], a0, bp.x); ffma2(ACC[1], a0, bp.y);               \
        ffma2(ACC[2], a1, bp.x); ffma2(ACC[3], a1, bp.y);               \
        ffma2(ACC[4], a2, bp.x); ffma2(ACC[5], a2, bp.y);               \
        ffma2(ACC[6], a3, bp.x); ffma2(ACC[7], a3, bp.y);               \
    }

// ---------------------------------------------------------------------------
// q block means (k means fused into k_kvz). grid 512, block 256.
// ---------------------------------------------------------------------------
__global__ void k_qmean(const float* __restrict__ q) {
    int blk = blockIdx.x * 4 + (threadIdx.x >> 6);
    int d = threadIdx.x & 63;
    const float* base = q + (size_t)blk * 64 * Dd + d;
    float s = 0.f;
#pragma unroll
    for (int r = 0; r < 64; r++) s += base[r * Dd];
    g_qb[blk * Dd + d] = s * (1.f / 64.f);
}

// ---------------------------------------------------------------------------
__global__ void k_topk() {
    int bh = blockIdx.x >> 6, qb = blockIdx.x & 63;
    __shared__ float qrow[Dd];
    __shared__ float sc[NBLK];
    int t = threadIdx.x;
    qrow[t] = g_qb[(bh * NBLK + qb) * Dd + t];
    __syncthreads();
    const float* kb = g_kb + (bh * NBLK + t) * Dd;
    float acc = 0.f;
#pragma unroll
    for (int d = 0; d < Dd; d++) acc += qrow[d] * kb[d];
    sc[t] = acc * SCALE;
    __syncthreads();
    if (t == 0) {
        for (int s = 0; s < TSEL; s++) {
            float best = -3.4e38f; int bi = 0;
            for (int j = 0; j < NBLK; j++)
                if (sc[j] > best) { best = sc[j]; bi = j; }
            g_lut[(bh * NBLK + qb) * TSEL + s] = bi;
            sc[bi] = -3.4e38f;
        }
    }
}

// ---------------------------------------------------------------------------
// K3: kv = phi(k)^T v, z = sum phi(k), and (fused) k block means.
// ---------------------------------------------------------------------------
__global__ void __launch_bounds__(256) k_kvz(const float* __restrict__ k,
                                             const float* __restrict__ v) {
    __shared__ float ck[64 * P68];
    __shared__ float vs[64 * P68];
    int tid = threadIdx.x;
    int bh = blockIdx.x >> 6, kb = blockIdx.x & 63;
    size_t goff = ((size_t)bh * Ll + kb * 64) * Dd;
    int vm = tid >> 4, ve = (tid & 15) * 4;
#pragma unroll
    for (int p = 0; p < 4; p++) {
        int m = vm + p * 16;
        *(float4*)&ck[m * P68 + ve] = *(const float4*)&k[goff + (size_t)m * 64 + ve];
        *(float4*)&vs[m * P68 + ve] = *(const float4*)&v[goff + (size_t)m * 64 + ve];
    }
    __syncthreads();
    // fused k block mean (before in-place softmax)
    if (tid < 64) {
        float s = 0.f;
#pragma unroll
        for (int m = 0; m < 64; m++) s += ck[m * P68 + tid];
        g_kb[(bh * NBLK + kb) * Dd + tid] = s * (1.f / 64.f);
    }
    __syncthreads();
    int warp = tid >> 5, lane = tid & 31;
    for (int r = warp; r < 64; r += 8) {
        float e0 = __expf(ck[r * P68 + lane]);
        float e1 = __expf(ck[r * P68 + lane + 32]);
        float s = e0 + e1;
#pragma unroll
        for (int o = 16; o; o >>= 1) s += __shfl_xor_sync(~0u, s, o);
        float inv = 1.f / s;
        ck[r * P68 + lane] = e0 * inv;
        ck[r * P68 + lane + 32] = e1 * inv;
    }
    __syncthreads();
    int tr = tid >> 4, tc = tid & 15;
    ull acc2[8];
#pragma unroll
    for (int i = 0; i < 8; i++) acc2[i] = 0ull;
#pragma unroll 16
    for (int m = 0; m < 64; m++)
        GSTEP(&ck[m * P68 + tr * 4], &vs[m * P68 + tc * 4], acc2);
    float* kvout = g_kv + ((size_t)(bh * NBLK + kb)) * Dd * Dd;
#pragma unroll
    for (int i = 0; i < 4; i++) {
        float2 c01 = unpk(acc2[i * 2]), c23 = unpk(acc2[i * 2 + 1]);
        *(float4*)&kvout[(tr * 4 + i) * Dd + tc * 4] =
            make_float4(c01.x, c01.y, c23.x, c23.y);
    }
    if (tid < 64) {
        float s = 0.f;
#pragma unroll
        for (int m = 0; m < 64; m++) s += ck[m * P68 + tid];
        g_z[(bh * NBLK + kb) * Dd + tid] = s;
    }
}

// ---------------------------------------------------------------------------
// K4: totals, vectorized. grid (BH,4), block 256.
// ---------------------------------------------------------------------------
__global__ void k_totals() {
    int bh = blockIdx.x, tid = threadIdx.x;
    int e4 = blockIdx.y * 1024 + tid * 4;
    const float* p = g_kv + (size_t)bh * NBLK * Dd * Dd + e4;
    float4 s = make_float4(0.f, 0.f, 0.f, 0.f);
#pragma unroll 8
    for (int kb = 0; kb < NBLK; kb++) {
        float4 x = *(const float4*)&p[(size_t)kb * Dd * Dd];
        s.x += x.x; s.y += x.y; s.z += x.z; s.w += x.w;
    }
    *(float4*)&g_kvtot[bh * Dd * Dd + e4] = s;
    if (blockIdx.y == 0 && tid < Dd) {
        const float* pz = g_z + bh * NBLK * Dd + tid;
        float sz = 0.f;
#pragma unroll 8
        for (int kb = 0; kb < NBLK; kb++) sz += pz[kb * Dd];
        g_ztot[bh * Dd + tid] = sz;
    }
}

// ---------------------------------------------------------------------------
// K5: tf32 mma main kernel, fragment-major operand staging.
// smem floats: Qb 0..4352 | FK0 4352 | FK1 8608 | FV0 12864 | FV1 17120 |
//              PF 21376 (4096) | zns 25472 | bl 25536 | den 25600  -> 25664
// Epilogue overlays: NbT(kvns^T,[e][d] pitch68) on FK0+, Wb([c][e] pitch68) on FV0+.
// ---------------------------------------------------------------------------
__global__ void __launch_bounds__(256, 2) k_main(
    const float* __restrict__ q, const float* __restrict__ k,
    const float* __restrict__ v, const float* __restrict__ W,
    const float* __restrict__ b, float* __restrict__ out)
{
    extern __shared__ float sm[];
    float* Qb  = sm;
    float* FK0 = sm + 4352;
    float* FK1 = sm + 8608;
    float* FV0 = sm + 12864;
    float* FV1 = sm + 17120;
    float* PF  = sm + 21376;
    float* zns = sm + 25472;
    float* bl  = sm + 25536;
    float* den = sm + 25600;
    __shared__ int lut[8];

    int tid = threadIdx.x;
    int bh = blockIdx.x >> 6, qb = blockIdx.x & 63;
    size_t qoff = ((size_t)bh * Ll + qb * 64) * Dd;

    if (tid < TSEL) lut[tid] = g_lut[(bh * NBLK + qb) * TSEL + tid];
    if (tid < 64) bl[tid] = b[tid];

    // stage Q raw (coalesced float4)
#pragma unroll
    for (int i = 0; i < 4; i++) {
        int idx = tid + 256 * i;
        int row = idx >> 4, c4 = (idx & 15) * 4;
        *(float4*)&Qb[row * P68 + c4] = *(const float4*)&q[qoff + (size_t)row * 64 + c4];
    }
    __syncthreads();   // lut visible

    // ---- frag-major staging helpers (as lambdas via macros) ----
#define STAGE_K_FRAG(FKU, ko, idx)                                        \
    {                                                                     \
        int row_ = (idx) >> 4, c4_ = ((idx) & 15) * 4;                    \
        float4 f_ = *(const float4*)&k[(ko) + (size_t)row_ * 64 + c4_];   \
        int nt_ = row_ >> 3, grp_ = row_ & 7;                             \
        int k8_ = c4_ >> 3, half_ = (c4_ >> 2) & 1;                       \
        int b_ = k8_ * FK_S8 + nt_ * FK_SN + grp_ * 8 + half_;            \
        (FKU)[b_ + 0] = cvt_tf32(f_.x); (FKU)[b_ + 2] = cvt_tf32(f_.y);   \
        (FKU)[b_ + 4] = cvt_tf32(f_.z); (FKU)[b_ + 6] = cvt_tf32(f_.w);   \
    }
#define STAGE_V_FRAG(FVU, vo, idx)                                        \
    {                                                                     \
        int row_ = (idx) >> 4, c4_ = ((idx) & 15) * 4;                    \
        float4 f_ = *(const float4*)&v[(vo) + (size_t)row_ * 64 + c4_];   \
        int m8_ = row_ >> 3, tig_ = (row_ & 3), hi_ = (row_ & 7) >> 2;    \
        int nt_ = c4_ >> 3, gb_ = (c4_ & 7);                              \
        int b_ = m8_ * FK_S8 + nt_ * FK_SN + tig_ * 2 + hi_;              \
        (FVU)[b_ + (gb_ + 0) * 8] = cvt_tf32(f_.x);                       \
        (FVU)[b_ + (gb_ + 1) * 8] = cvt_tf32(f_.y);                       \
        (FVU)[b_ + (gb_ + 2) * 8] = cvt_tf32(f_.z);                       \
        (FVU)[b_ + (gb_ + 3) * 8] = cvt_tf32(f_.w);                       \
    }

    // stage K/V block 0 (all 256 threads)
    {
        size_t ko = ((size_t)bh * Ll + (size_t)lut[0] * 64) * Dd;
        unsigned* KU = (unsigned*)FK0;
        unsigned* VU = (unsigned*)FV0;
#pragma unroll
        for (int i = 0; i < 4; i++) { int idx = tid + 256 * i; STAGE_K_FRAG(KU, ko, idx); }
#pragma unroll
        for (int i = 0; i < 4; i++) { int idx = tid + 256 * i; STAGE_V_FRAG(VU, ko, idx); }
    }
    __syncthreads();

    int wid = tid >> 5, lane = tid & 31;
    int grp = lane >> 2, tig = lane & 3;
    int r0 = (wid & 3) * 16;
    unsigned* PFw = (unsigned*)(PF + (wid & 3) * 1024);

    // preload Q A-fragments (reused across all t)
    unsigned AQ[8][4];
    if (wid < 4) {
#pragma unroll
        for (int k8 = 0; k8 < 8; k8++) {
            int k0 = 8 * k8;
            AQ[k8][0] = cvt_tf32(Qb[(r0 + grp) * P68 + k0 + tig]);
            AQ[k8][1] = cvt_tf32(Qb[(r0 + grp + 8) * P68 + k0 + tig]);
            AQ[k8][2] = cvt_tf32(Qb[(r0 + grp) * P68 + k0 + tig + 4]);
            AQ[k8][3] = cvt_tf32(Qb[(r0 + grp + 8) * P68 + k0 + tig + 4]);
        }
    }

    float OS[8][4];
#pragma unroll
    for (int i = 0; i < 8; i++)
#pragma unroll
        for (int j = 0; j < 4; j++) OS[i][j] = 0.f;
    float lp0 = 0.f, lp1 = 0.f;

    // precomputed PF write offsets for this thread
    int cc0 = 2 * tig;
    int phi = cc0 >> 2;                 // same for cc0 and cc0+1
    int pa0 = 16 * grp + 4 * (cc0 & 3) + 2 * phi;
    int pa1 = 16 * grp + 4 * ((cc0 + 1) & 3) + 2 * phi;

    for (int t = 0; t < TSEL; t++) {
        const uint2* FKU2 = (const uint2*)((t & 1) ? FK1 : FK0);
        const uint2* FVU2 = (const uint2*)((t & 1) ? FV1 : FV0);
        if (wid < 4) {
            // ---- S = Q K^T ----
            float Sc[8][4];
#pragma unroll
            for (int i = 0; i < 8; i++)
#pragma unroll
                for (int j = 0; j < 4; j++) Sc[i][j] = 0.f;
#pragma unroll
            for (int k8 = 0; k8 < 8; k8++) {
#pragma unroll
                for (int nt = 0; nt < 8; nt++) {
                    uint2 bb = FKU2[k8 * (FK_S8 / 2) + nt * (FK_SN / 2) + lane];
                    mma_tf32(Sc[nt], AQ[k8][0], AQ[k8][1], AQ[k8][2], AQ[k8][3],
                             bb.x, bb.y);
                }
            }
            // ---- exp (no max), write P in A-frag layout ----
#pragma unroll
            for (int nt = 0; nt < 8; nt++) {
                float e0 = __expf(Sc[nt][0] * SCALE), e1 = __expf(Sc[nt][1] * SCALE);
                float e2 = __expf(Sc[nt][2] * SCALE), e3 = __expf(Sc[nt][3] * SCALE);
                lp0 += e0 + e1; lp1 += e2 + e3;
                PFw[nt * 128 + pa0]     = cvt_tf32(e0);
                PFw[nt * 128 + pa0 + 1] = cvt_tf32(e2);
                PFw[nt * 128 + pa1]     = cvt_tf32(e1);
                PFw[nt * 128 + pa1 + 1] = cvt_tf32(e3);
            }
            __syncwarp();
            // ---- o_s += P V ----
#pragma unroll
            for (int m8 = 0; m8 < 8; m8++) {
                uint4 ap = *(const uint4*)&PFw[m8 * 128 + lane * 4];
#pragma unroll
                for (int nt = 0; nt < 8; nt++) {
                    uint2 bb = FVU2[m8 * (FK_S8 / 2) + nt * (FK_SN / 2) + lane];
                    mma_tf32(OS[nt], ap.x, ap.y, ap.z, ap.w, bb.x, bb.y);
                }
            }
        } else if (t + 1 < TSEL) {
            // ---- producers: stage K/V for t+1 in frag layout ----
            int ptid = tid - 128;
            size_t ko = ((size_t)bh * Ll + (size_t)lut[t + 1] * 64) * Dd;
            unsigned* KU2 = (unsigned*)((t & 1) ? FK0 : FK1);
            unsigned* VU2 = (unsigned*)((t & 1) ? FV0 : FV1);
#pragma unroll
            for (int i = 0; i < 8; i++) { int idx = ptid + 128 * i; STAGE_K_FRAG(KU2, ko, idx); }
#pragma unroll
            for (int i = 0; i < 8; i++) { int idx = ptid + 128 * i; STAGE_V_FRAG(VU2, ko, idx); }
        }
        __syncthreads();
    }

    // row sums of exp
    float l0 = lp0, l1 = lp1;
    l0 += __shfl_xor_sync(~0u, l0, 1); l0 += __shfl_xor_sync(~0u, l0, 2);
    l1 += __shfl_xor_sync(~0u, l1, 1); l1 += __shfl_xor_sync(~0u, l1, 2);

    // ---- c_q = softmax(q) over D (no max; thread per row, in place) ----
    if (tid < 64) {
        float s = 0.f;
#pragma unroll 8
        for (int d = 0; d < 64; d++) {
            float e = __expf(Qb[tid * P68 + d]);
            Qb[tid * P68 + d] = e; s += e;
        }
        float inv = 1.f / s;
#pragma unroll 8
        for (int d = 0; d < 64; d++) Qb[tid * P68 + d] *= inv;
    }

    // ---- kvns^T into NbT (tf32, [e][d] pitch 68), z_ns; W into Wb (tf32) ----
    {
        unsigned* NU = (unsigned*)FK0;   // NbT overlays FK0 (+ spill into FK1)
        int d0 = tid >> 2, e0 = (tid & 3) * 16;
        const float* kvt = g_kvtot + bh * Dd * Dd;
#pragma unroll
        for (int p = 0; p < 4; p++) {
            float4 s = *(const float4*)&kvt[d0 * 64 + e0 + 4 * p];
#pragma unroll
            for (int t = 0; t < TSEL; t++) {
                const float4 x = *(const float4*)
                    &g_kv[((size_t)(bh * NBLK + lut[t])) * Dd * Dd + d0 * 64 + e0 + 4 * p];
                s.x -= x.x; s.y -= x.y; s.z -= x.z; s.w -= x.w;
            }
            NU[(e0 + 4 * p + 0) * P68 + d0] = cvt_tf32(s.x);
            NU[(e0 + 4 * p + 1) * P68 + d0] = cvt_tf32(s.y);
            NU[(e0 + 4 * p + 2) * P68 + d0] = cvt_tf32(s.z);
            NU[(e0 + 4 * p + 3) * P68 + d0] = cvt_tf32(s.w);
        }
        if (tid < 64) {
            float s = g_ztot[bh * Dd + tid];
#pragma unroll
            for (int t = 0; t < TSEL; t++) s -= g_z[(bh * NBLK + lut[t]) * Dd + tid];
            zns[tid] = s;
        }
        unsigned* WU = (unsigned*)FV0;   // Wb overlays FV0 (+ spill into FV1)
#pragma unroll
        for (int i = 0; i < 4; i++) {
            int idx = tid + 256 * i;
            int row = idx >> 4, c4 = (idx & 15) * 4;
            float4 f = *(const float4*)&W[row * 64 + c4];
            *(uint4*)&WU[row * P68 + c4] =
                make_uint4(cvt_tf32(f.x), cvt_tf32(f.y), cvt_tf32(f.z), cvt_tf32(f.w));
        }
    }
    __syncthreads();

    // ---- den ----
    if (tid < 64) {
        float s = 0.f;
#pragma unroll 8
        for (int d = 0; d < 64; d++) s += Qb[tid * P68 + d] * zns[d];
        den[tid] = s;
    }
    __syncthreads();

    if (wid < 4) {
        const unsigned* NU = (const unsigned*)FK0;
        const unsigned* WU = (const unsigned*)FV0;
        // ---- num = c_q kv_ns ----
        float OL[8][4];
#pragma unroll
        for (int i = 0; i < 8; i++)
#pragma unroll
            for (int j = 0; j < 4; j++) OL[i][j] = 0.f;
#pragma unroll
        for (int k8 = 0; k8 < 8; k8++) {
            int k0 = 8 * k8;
            unsigned a0 = cvt_tf32(Qb[(r0 + grp) * P68 + k0 + tig]);
            unsigned a1 = cvt_tf32(Qb[(r0 + grp + 8) * P68 + k0 + tig]);
            unsigned a2 = cvt_tf32(Qb[(r0 + grp) * P68 + k0 + tig + 4]);
            unsigned a3 = cvt_tf32(Qb[(r0 + grp + 8) * P68 + k0 + tig + 4]);
#pragma unroll
            for (int nt = 0; nt < 8; nt++) {
                unsigned b0 = NU[(8 * nt + grp) * P68 + k0 + tig];
                unsigned b1 = NU[(8 * nt + grp) * P68 + k0 + tig + 4];
                mma_tf32(OL[nt], a0, a1, a2, a3, b0, b1);
            }
        }
        float i0 = 1.f / (den[r0 + grp] + 1e-6f);
        float i1 = 1.f / (den[r0 + grp + 8] + 1e-6f);
        // write o_l in A-frag layout into PF
#pragma unroll
        for (int nt = 0; nt < 8; nt++) {
            PFw[nt * 128 + pa0]     = cvt_tf32(OL[nt][0] * i0);
            PFw[nt * 128 + pa0 + 1] = cvt_tf32(OL[nt][2] * i1);
            PFw[nt * 128 + pa1]     = cvt_tf32(OL[nt][1] * i0);
            PFw[nt * 128 + pa1 + 1] = cvt_tf32(OL[nt][3] * i1);
        }
        __syncwarp();
        // ---- proj = o_l W^T ----
        float PR[8][4];
#pragma unroll
        for (int i = 0; i < 8; i++)
#pragma unroll
            for (int j = 0; j < 4; j++) PR[i][j] = 0.f;
#pragma unroll
        for (int k8 = 0; k8 < 8; k8++) {
            int k0 = 8 * k8;
            uint4 ap = *(const uint4*)&PFw[k8 * 128 + lane * 4];
#pragma unroll
            for (int nt = 0; nt < 8; nt++) {
                unsigned b0 = WU[(8 * nt + grp) * P68 + k0 + tig];
                unsigned b1 = WU[(8 * nt + grp) * P68 + k0 + tig + 4];
                mma_tf32(PR[nt], ap.x, ap.y, ap.z, ap.w, b0, b1);
            }
        }
        // ---- write out ----
        float inv0 = 1.f / l0, inv1 = 1.f / l1;
#pragma unroll
        for (int nt = 0; nt < 8; nt++) {
            int c = 8 * nt + 2 * tig;
            float2 bv = *(float2*)&bl[c];
            *(float2*)&out[qoff + (size_t)(r0 + grp) * 64 + c] =
                make_float2(OS[nt][0] * inv0 + PR[nt][0] + bv.x,
                            OS[nt][1] * inv0 + PR[nt][1] + bv.y);
            *(float2*)&out[qoff + (size_t)(r0 + grp + 8) * 64 + c] =
                make_float2(OS[nt][2] * inv1 + PR[nt][2] + bv.x,
                            OS[nt][3] * inv1 + PR[nt][3] + bv.y);
        }
    }
}

// ---------------------------------------------------------------------------
extern "C" void kernel_launch(void* const* d_in, const int* in_sizes, int n_in,
                              void* d_out, int out_size) {
    const float* q = (const float*)d_in[0];
    const float* k = (const float*)d_in[1];
    const float* v = (const float*)d_in[2];
    const float* W = (const float*)d_in[3];
    const float* b = (const float*)d_in[4];
    float* out = (float*)d_out;

    int smem_main = 25664 * (int)sizeof(float);
    cudaFuncSetAttribute(k_main, cudaFuncAttributeMaxDynamicSharedMemorySize, smem_main);

    k_qmean<<<512, 256>>>(q);
    k_kvz<<<BH * NBLK, 256>>>(k, v);
    k_topk<<<BH * NBLK, 64>>>();
    k_totals<<<dim3(BH, 4), 256>>>();
    k_main<<<BH * NBLK, 256, smem_main>>>(q, k, v, W, b, out);
}

// round 13
// speedup vs baseline: 1.0102x; 1.0102x over previous
#include <cuda_runtime.h>
#include <cuda_bf16.h>
#include <math.h>

#define Ll 4096
#define Dd 64
#define BH 32
#define NBLK 64
#define TSEL 6
#define SCALE 0.125f
#define P68 68

typedef unsigned long long ull;

__device__ __forceinline__ ull dup2(float x) {
    ull r; asm("mov.b64 %0, {%1, %1};" : "=l"(r) : "f"(x)); return r;
}
__device__ __forceinline__ void ffma2(ull& d, ull a, ull b) {
    asm("fma.rn.f32x2 %0, %1, %2, %3;" : "=l"(d) : "l"(a), "l"(b), "l"(d));
}
__device__ __forceinline__ float2 unpk(ull v) {
    float2 f; asm("mov.b64 {%0, %1}, %2;" : "=f"(f.x), "=f"(f.y) : "l"(v)); return f;
}
__device__ __forceinline__ unsigned cvt_tf32(float x) {
    unsigned r; asm("cvt.rna.tf32.f32 %0, %1;" : "=r"(r) : "f"(x)); return r;
}
__device__ __forceinline__ void mma_tf32(float* c,
    unsigned a0, unsigned a1, unsigned a2, unsigned a3,
    unsigned b0, unsigned b1) {
    asm volatile(
        "mma.sync.aligned.m16n8k8.row.col.f32.tf32.tf32.f32 "
        "{%0,%1,%2,%3}, {%4,%5,%6,%7}, {%8,%9}, {%0,%1,%2,%3};"
        : "+f"(c[0]), "+f"(c[1]), "+f"(c[2]), "+f"(c[3])
        : "r"(a0), "r"(a1), "r"(a2), "r"(a3), "r"(b0), "r"(b1));
}

__device__ float g_qb[BH * NBLK * Dd];
__device__ float g_kb[BH * NBLK * Dd];
__device__ int   g_lut[BH * NBLK * TSEL];
__device__ float g_kv[(size_t)BH * NBLK * Dd * Dd];
__device__ float g_z[BH * NBLK * Dd];
__device__ float g_kvtot[BH * Dd * Dd];
__device__ float g_ztot[BH * Dd];

#define GSTEP(Abase, Bbase, ACC)                                        \
    {                                                                   \
        float4 af = *(const float4*)(Abase);                            \
        ulonglong2 bp = *(const ulonglong2*)(Bbase);                    \
        ull a0 = dup2(af.x), a1 = dup2(af.y), a2 = dup2(af.z), a3 = dup2(af.w); \
        ffma2(ACC[0], a0, bp.x); ffma2(ACC[1], a0, bp.y);               \
        ffma2(ACC[2], a1, bp.x); ffma2(ACC[3], a1, bp.y);               \
        ffma2(ACC[4], a2, bp.x); ffma2(ACC[5], a2, bp.y);               \
        ffma2(ACC[6], a3, bp.x); ffma2(ACC[7], a3, bp.y);               \
    }

// ---------------------------------------------------------------------------
// q block means only (k means fused into k_kvz). grid 512, block 256.
// ---------------------------------------------------------------------------
__global__ void k_qmean(const float* __restrict__ q) {
    int blk = blockIdx.x * 4 + (threadIdx.x >> 6);
    int d = threadIdx.x & 63;
    const float* base = q + (size_t)blk * 64 * Dd + d;
    float s = 0.f;
#pragma unroll
    for (int r = 0; r < 64; r++) s += base[r * Dd];
    g_qb[blk * Dd + d] = s * (1.f / 64.f);
}

// ---------------------------------------------------------------------------
__global__ void k_topk() {
    int bh = blockIdx.x >> 6, qb = blockIdx.x & 63;
    __shared__ float qrow[Dd];
    __shared__ float sc[NBLK];
    int t = threadIdx.x;
    qrow[t] = g_qb[(bh * NBLK + qb) * Dd + t];
    __syncthreads();
    const float* kb = g_kb + (bh * NBLK + t) * Dd;
    float acc = 0.f;
#pragma unroll
    for (int d = 0; d < Dd; d++) acc += qrow[d] * kb[d];
    sc[t] = acc * SCALE;
    __syncthreads();
    if (t == 0) {
        for (int s = 0; s < TSEL; s++) {
            float best = -3.4e38f; int bi = 0;
            for (int j = 0; j < NBLK; j++)
                if (sc[j] > best) { best = sc[j]; bi = j; }
            g_lut[(bh * NBLK + qb) * TSEL + s] = bi;
            sc[bi] = -3.4e38f;
        }
    }
}

// ---------------------------------------------------------------------------
// K3: kv = phi(k)^T v, z = sum phi(k), and fused k block means.
// ---------------------------------------------------------------------------
__global__ void __launch_bounds__(256) k_kvz(const float* __restrict__ k,
                                             const float* __restrict__ v) {
    __shared__ float ck[64 * P68];
    __shared__ float vs[64 * P68];
    int tid = threadIdx.x;
    int bh = blockIdx.x >> 6, kb = blockIdx.x & 63;
    size_t goff = ((size_t)bh * Ll + kb * 64) * Dd;
    int vm = tid >> 4, ve = (tid & 15) * 4;
#pragma unroll
    for (int p = 0; p < 4; p++) {
        int m = vm + p * 16;
        *(float4*)&ck[m * P68 + ve] = *(const float4*)&k[goff + (size_t)m * 64 + ve];
        *(float4*)&vs[m * P68 + ve] = *(const float4*)&v[goff + (size_t)m * 64 + ve];
    }
    __syncthreads();
    // fused k block mean (before in-place softmax)
    if (tid < 64) {
        float s = 0.f;
#pragma unroll
        for (int m = 0; m < 64; m++) s += ck[m * P68 + tid];
        g_kb[(bh * NBLK + kb) * Dd + tid] = s * (1.f / 64.f);
    }
    __syncthreads();
    int warp = tid >> 5, lane = tid & 31;
    for (int r = warp; r < 64; r += 8) {
        float e0 = __expf(ck[r * P68 + lane]);
        float e1 = __expf(ck[r * P68 + lane + 32]);
        float s = e0 + e1;
#pragma unroll
        for (int o = 16; o; o >>= 1) s += __shfl_xor_sync(~0u, s, o);
        float inv = 1.f / s;
        ck[r * P68 + lane] = e0 * inv;
        ck[r * P68 + lane + 32] = e1 * inv;
    }
    __syncthreads();
    int tr = tid >> 4, tc = tid & 15;
    ull acc2[8];
#pragma unroll
    for (int i = 0; i < 8; i++) acc2[i] = 0ull;
#pragma unroll 16
    for (int m = 0; m < 64; m++)
        GSTEP(&ck[m * P68 + tr * 4], &vs[m * P68 + tc * 4], acc2);
    float* kvout = g_kv + ((size_t)(bh * NBLK + kb)) * Dd * Dd;
#pragma unroll
    for (int i = 0; i < 4; i++) {
        float2 c01 = unpk(acc2[i * 2]), c23 = unpk(acc2[i * 2 + 1]);
        *(float4*)&kvout[(tr * 4 + i) * Dd + tc * 4] =
            make_float4(c01.x, c01.y, c23.x, c23.y);
    }
    if (tid < 64) {
        float s = 0.f;
#pragma unroll
        for (int m = 0; m < 64; m++) s += ck[m * P68 + tid];
        g_z[(bh * NBLK + kb) * Dd + tid] = s;
    }
}

// ---------------------------------------------------------------------------
// K4: totals (R10 version: grid (BH,16), block 256)
// ---------------------------------------------------------------------------
__global__ void k_totals() {
    int bh = blockIdx.x, tid = threadIdx.x;
    int e = blockIdx.y * 256 + tid;
    const float* p = g_kv + (size_t)bh * NBLK * Dd * Dd + e;
    float s = 0.f;
#pragma unroll 8
    for (int kb = 0; kb < NBLK; kb++) s += p[(size_t)kb * Dd * Dd];
    g_kvtot[bh * Dd * Dd + e] = s;
    if (blockIdx.y == 0 && tid < Dd) {
        const float* pz = g_z + bh * NBLK * Dd + tid;
        float sz = 0.f;
#pragma unroll 8
        for (int kb = 0; kb < NBLK; kb++) sz += pz[kb * Dd];
        g_ztot[bh * Dd + tid] = sz;
    }
}

// ---------------------------------------------------------------------------
// K5: tf32 mma main kernel (R10 layouts) + hoisted Q A-fragments.
// Qb staged pre-rounded to tf32. smem = 26304 floats = 105.2KB, occ 2.
// ---------------------------------------------------------------------------
__global__ void __launch_bounds__(256, 2) k_main(
    const float* __restrict__ q, const float* __restrict__ k,
    const float* __restrict__ v, const float* __restrict__ W,
    const float* __restrict__ b, float* __restrict__ out)
{
    extern __shared__ float sm[];
    float* Qb  = sm;            // tf32-rounded Q; later c_q
    float* Pb  = sm + 4352;     // tf32 P; later tf32 o_l
    float* Kb0 = sm + 8704;     // tf32 K (buf0); later tf32 kvns^T
    float* Kb1 = sm + 13056;    // tf32 K (buf1)
    float* VT0 = sm + 17408;    // tf32 V^T (buf0); later tf32 W
    float* VT1 = sm + 21760;    // tf32 V^T (buf1)
    float* zns = sm + 26112;
    float* bl  = sm + 26176;
    float* den = sm + 26240;
    __shared__ int lut[8];

    int tid = threadIdx.x;
    int bh = blockIdx.x >> 6, qb = blockIdx.x & 63;
    size_t qoff = ((size_t)bh * Ll + qb * 64) * Dd;

    if (tid < TSEL) lut[tid] = g_lut[(bh * NBLK + qb) * TSEL + tid];
    if (tid < 64) bl[tid] = b[tid];

    // stage Q pre-rounded to tf32 (valid fp32 bit patterns)
    {
        unsigned* QU = (unsigned*)Qb;
#pragma unroll
        for (int i = 0; i < 4; i++) {
            int idx = tid + 256 * i;
            int row = idx >> 4, c4 = (idx & 15) * 4;
            float4 f = *(const float4*)&q[qoff + (size_t)row * 64 + c4];
            *(uint4*)&QU[row * P68 + c4] =
                make_uint4(cvt_tf32(f.x), cvt_tf32(f.y), cvt_tf32(f.z), cvt_tf32(f.w));
        }
    }
    __syncthreads();   // lut visible

    // stage K/V block 0 (all threads)
    {
        size_t ko = ((size_t)bh * Ll + (size_t)lut[0] * 64) * Dd;
        unsigned* KU = (unsigned*)Kb0;
#pragma unroll
        for (int i = 0; i < 4; i++) {
            int idx = tid + 256 * i;
            int row = idx >> 4, c4 = (idx & 15) * 4;
            float4 f = *(const float4*)&k[ko + (size_t)row * 64 + c4];
            *(uint4*)&KU[row * P68 + c4] =
                make_uint4(cvt_tf32(f.x), cvt_tf32(f.y), cvt_tf32(f.z), cvt_tf32(f.w));
        }
        unsigned* VU = (unsigned*)VT0;
        int dd = tid & 63, h16 = (tid >> 6) * 16;
#pragma unroll
        for (int r = 0; r < 16; r++)
            VU[dd * P68 + h16 + r] = cvt_tf32(v[ko + (size_t)(h16 + r) * 64 + dd]);
    }
    __syncthreads();

    int wid = tid >> 5, lane = tid & 31;
    int grp = lane >> 2, tig = lane & 3;
    int r0 = (wid & 3) * 16;
    unsigned* PbU = (unsigned*)Pb;
    const unsigned* QU = (const unsigned*)Qb;

    // hoist Q A-fragments into registers (reused across all 6 t-iterations)
    unsigned AQ[8][4];
    if (wid < 4) {
#pragma unroll
        for (int k8 = 0; k8 < 8; k8++) {
            int k0 = 8 * k8;
            AQ[k8][0] = QU[(r0 + grp) * P68 + k0 + tig];
            AQ[k8][1] = QU[(r0 + grp + 8) * P68 + k0 + tig];
            AQ[k8][2] = QU[(r0 + grp) * P68 + k0 + tig + 4];
            AQ[k8][3] = QU[(r0 + grp + 8) * P68 + k0 + tig + 4];
        }
    }

    float OS[8][4];
#pragma unroll
    for (int i = 0; i < 8; i++)
#pragma unroll
        for (int j = 0; j < 4; j++) OS[i][j] = 0.f;
    float lp0 = 0.f, lp1 = 0.f;

    for (int t = 0; t < TSEL; t++) {
        const unsigned* KU = (const unsigned*)((t & 1) ? Kb1 : Kb0);
        const unsigned* VU = (const unsigned*)((t & 1) ? VT1 : VT0);
        if (wid < 4) {
            // ---- S = Q K^T ----
            float Sc[8][4];
#pragma unroll
            for (int i = 0; i < 8; i++)
#pragma unroll
                for (int j = 0; j < 4; j++) Sc[i][j] = 0.f;
#pragma unroll
            for (int k8 = 0; k8 < 8; k8++) {
                int k0 = 8 * k8;
#pragma unroll
                for (int nt = 0; nt < 8; nt++) {
                    unsigned b0 = KU[(8 * nt + grp) * P68 + k0 + tig];
                    unsigned b1 = KU[(8 * nt + grp) * P68 + k0 + tig + 4];
                    mma_tf32(Sc[nt], AQ[k8][0], AQ[k8][1], AQ[k8][2], AQ[k8][3], b0, b1);
                }
            }
            // ---- exp (no max), write tf32 P, accumulate row sums ----
#pragma unroll
            for (int nt = 0; nt < 8; nt++) {
                float e0 = __expf(Sc[nt][0] * SCALE), e1 = __expf(Sc[nt][1] * SCALE);
                float e2 = __expf(Sc[nt][2] * SCALE), e3 = __expf(Sc[nt][3] * SCALE);
                lp0 += e0 + e1; lp1 += e2 + e3;
                *(uint2*)&PbU[(r0 + grp) * P68 + 8 * nt + 2 * tig] =
                    make_uint2(cvt_tf32(e0), cvt_tf32(e1));
                *(uint2*)&PbU[(r0 + grp + 8) * P68 + 8 * nt + 2 * tig] =
                    make_uint2(cvt_tf32(e2), cvt_tf32(e3));
            }
            __syncwarp();
            // ---- o_s += P V ----
#pragma unroll
            for (int k8 = 0; k8 < 8; k8++) {
                int m0 = 8 * k8;
                unsigned a0 = PbU[(r0 + grp) * P68 + m0 + tig];
                unsigned a1 = PbU[(r0 + grp + 8) * P68 + m0 + tig];
                unsigned a2 = PbU[(r0 + grp) * P68 + m0 + tig + 4];
                unsigned a3 = PbU[(r0 + grp + 8) * P68 + m0 + tig + 4];
#pragma unroll
                for (int nt = 0; nt < 8; nt++) {
                    unsigned b0 = VU[(8 * nt + grp) * P68 + m0 + tig];
                    unsigned b1 = VU[(8 * nt + grp) * P68 + m0 + tig + 4];
                    mma_tf32(OS[nt], a0, a1, a2, a3, b0, b1);
                }
            }
        } else if (t + 1 < TSEL) {
            // ---- producers: stage K/V for t+1 into the other buffer ----
            int ptid = tid - 128;
            size_t ko = ((size_t)bh * Ll + (size_t)lut[t + 1] * 64) * Dd;
            unsigned* KU2 = (unsigned*)((t & 1) ? Kb0 : Kb1);
            unsigned* VU2 = (unsigned*)((t & 1) ? VT0 : VT1);
#pragma unroll
            for (int i = 0; i < 8; i++) {
                int idx = ptid + 128 * i;
                int row = idx >> 4, c4 = (idx & 15) * 4;
                float4 f = *(const float4*)&k[ko + (size_t)row * 64 + c4];
                *(uint4*)&KU2[row * P68 + c4] =
                    make_uint4(cvt_tf32(f.x), cvt_tf32(f.y), cvt_tf32(f.z), cvt_tf32(f.w));
            }
            int dd = ptid & 63, h32 = (ptid >> 6) * 32;
#pragma unroll
            for (int r = 0; r < 32; r++)
                VU2[dd * P68 + h32 + r] = cvt_tf32(v[ko + (size_t)(h32 + r) * 64 + dd]);
        }
        __syncthreads();
    }

    // row sums of exp
    float l0 = lp0, l1 = lp1;
    l0 += __shfl_xor_sync(~0u, l0, 1); l0 += __shfl_xor_sync(~0u, l0, 2);
    l1 += __shfl_xor_sync(~0u, l1, 1); l1 += __shfl_xor_sync(~0u, l1, 2);

    // ---- c_q = softmax(q) over D (no max; thread per row, in place) ----
    if (tid < 64) {
        float s = 0.f;
#pragma unroll 8
        for (int d = 0; d < 64; d++) {
            float e = __expf(Qb[tid * P68 + d]);
            Qb[tid * P68 + d] = e; s += e;
        }
        float inv = 1.f / s;
#pragma unroll 8
        for (int d = 0; d < 64; d++) Qb[tid * P68 + d] *= inv;
    }

    // ---- kvns^T into Kb0 (tf32), z_ns; stage W into VT0 (tf32) ----
    {
        unsigned* NU = (unsigned*)Kb0;
        int d0 = tid >> 2, e0 = (tid & 3) * 16;
        const float* kvt = g_kvtot + bh * Dd * Dd;
#pragma unroll
        for (int p = 0; p < 4; p++) {
            float4 s = *(const float4*)&kvt[d0 * 64 + e0 + 4 * p];
#pragma unroll
            for (int t = 0; t < TSEL; t++) {
                const float4 x = *(const float4*)
                    &g_kv[((size_t)(bh * NBLK + lut[t])) * Dd * Dd + d0 * 64 + e0 + 4 * p];
                s.x -= x.x; s.y -= x.y; s.z -= x.z; s.w -= x.w;
            }
            NU[(e0 + 4 * p + 0) * P68 + d0] = cvt_tf32(s.x);
            NU[(e0 + 4 * p + 1) * P68 + d0] = cvt_tf32(s.y);
            NU[(e0 + 4 * p + 2) * P68 + d0] = cvt_tf32(s.z);
            NU[(e0 + 4 * p + 3) * P68 + d0] = cvt_tf32(s.w);
        }
        if (tid < 64) {
            float s = g_ztot[bh * Dd + tid];
#pragma unroll
            for (int t = 0; t < TSEL; t++) s -= g_z[(bh * NBLK + lut[t]) * Dd + tid];
            zns[tid] = s;
        }
        unsigned* WU = (unsigned*)VT0;
#pragma unroll
        for (int i = 0; i < 4; i++) {
            int idx = tid + 256 * i;
            int row = idx >> 4, c4 = (idx & 15) * 4;
            float4 f = *(const float4*)&W[row * 64 + c4];
            *(uint4*)&WU[row * P68 + c4] =
                make_uint4(cvt_tf32(f.x), cvt_tf32(f.y), cvt_tf32(f.z), cvt_tf32(f.w));
        }
    }
    __syncthreads();

    // ---- den ----
    if (tid < 64) {
        float s = 0.f;
#pragma unroll 8
        for (int d = 0; d < 64; d++) s += Qb[tid * P68 + d] * zns[d];
        den[tid] = s;
    }
    __syncthreads();

    if (wid < 4) {
        const unsigned* NU = (const unsigned*)Kb0;
        const unsigned* WU = (const unsigned*)VT0;
        // ---- num = c_q kv_ns ----
        float OL[8][4];
#pragma unroll
        for (int i = 0; i < 8; i++)
#pragma unroll
            for (int j = 0; j < 4; j++) OL[i][j] = 0.f;
#pragma unroll
        for (int k8 = 0; k8 < 8; k8++) {
            int k0 = 8 * k8;
            unsigned a0 = cvt_tf32(Qb[(r0 + grp) * P68 + k0 + tig]);
            unsigned a1 = cvt_tf32(Qb[(r0 + grp + 8) * P68 + k0 + tig]);
            unsigned a2 = cvt_tf32(Qb[(r0 + grp) * P68 + k0 + tig + 4]);
            unsigned a3 = cvt_tf32(Qb[(r0 + grp + 8) * P68 + k0 + tig + 4]);
#pragma unroll
            for (int nt = 0; nt < 8; nt++) {
                unsigned b0 = NU[(8 * nt + grp) * P68 + k0 + tig];
                unsigned b1 = NU[(8 * nt + grp) * P68 + k0 + tig + 4];
                mma_tf32(OL[nt], a0, a1, a2, a3, b0, b1);
            }
        }
        float i0 = 1.f / (den[r0 + grp] + 1e-6f);
        float i1 = 1.f / (den[r0 + grp + 8] + 1e-6f);
#pragma unroll
        for (int nt = 0; nt < 8; nt++) {
            *(uint2*)&PbU[(r0 + grp) * P68 + 8 * nt + 2 * tig] =
                make_uint2(cvt_tf32(OL[nt][0] * i0), cvt_tf32(OL[nt][1] * i0));
            *(uint2*)&PbU[(r0 + grp + 8) * P68 + 8 * nt + 2 * tig] =
                make_uint2(cvt_tf32(OL[nt][2] * i1), cvt_tf32(OL[nt][3] * i1));
        }
        __syncwarp();
        // ---- proj = o_l W^T ----
        float PR[8][4];
#pragma unroll
        for (int i = 0; i < 8; i++)
#pragma unroll
            for (int j = 0; j < 4; j++) PR[i][j] = 0.f;
#pragma unroll
        for (int k8 = 0; k8 < 8; k8++) {
            int k0 = 8 * k8;
            unsigned a0 = PbU[(r0 + grp) * P68 + k0 + tig];
            unsigned a1 = PbU[(r0 + grp + 8) * P68 + k0 + tig];
            unsigned a2 = PbU[(r0 + grp) * P68 + k0 + tig + 4];
            unsigned a3 = PbU[(r0 + grp + 8) * P68 + k0 + tig + 4];
#pragma unroll
            for (int nt = 0; nt < 8; nt++) {
                unsigned b0 = WU[(8 * nt + grp) * P68 + k0 + tig];
                unsigned b1 = WU[(8 * nt + grp) * P68 + k0 + tig + 4];
                mma_tf32(PR[nt], a0, a1, a2, a3, b0, b1);
            }
        }
        // ---- write out = o_s/l + proj + b ----
        float inv0 = 1.f / l0, inv1 = 1.f / l1;
#pragma unroll
        for (int nt = 0; nt < 8; nt++) {
            int c = 8 * nt + 2 * tig;
            float2 bv = *(float2*)&bl[c];
            *(float2*)&out[qoff + (size_t)(r0 + grp) * 64 + c] =
                make_float2(OS[nt][0] * inv0 + PR[nt][0] + bv.x,
                            OS[nt][1] * inv0 + PR[nt][1] + bv.y);
            *(float2*)&out[qoff + (size_t)(r0 + grp + 8) * 64 + c] =
                make_float2(OS[nt][2] * inv1 + PR[nt][2] + bv.x,
                            OS[nt][3] * inv1 + PR[nt][3] + bv.y);
        }
    }
}

// ---------------------------------------------------------------------------
extern "C" void kernel_launch(void* const* d_in, const int* in_sizes, int n_in,
                              void* d_out, int out_size) {
    const float* q = (const float*)d_in[0];
    const float* k = (const float*)d_in[1];
    const float* v = (const float*)d_in[2];
    const float* W = (const float*)d_in[3];
    const float* b = (const float*)d_in[4];
    float* out = (float*)d_out;

    int smem_main = 26304 * (int)sizeof(float);
    cudaFuncSetAttribute(k_main, cudaFuncAttributeMaxDynamicSharedMemorySize, smem_main);

    k_qmean<<<512, 256>>>(q);
    k_kvz<<<BH * NBLK, 256>>>(k, v);
    k_topk<<<BH * NBLK, 64>>>();
    k_totals<<<dim3(BH, 16), 256>>>();
    k_main<<<BH * NBLK, 256, smem_main>>>(q, k, v, W, b, out);
}

// round 16
// speedup vs baseline: 1.0604x; 1.0497x over previous
#include <cuda_runtime.h>
#include <cuda_bf16.h>
#include <math.h>

#define Ll 4096
#define Dd 64
#define BH 32
#define NBLK 64
#define TSEL 6
#define SCALE 0.125f
#define P68 68

typedef unsigned long long ull;

__device__ __forceinline__ ull dup2(float x) {
    ull r; asm("mov.b64 %0, {%1, %1};" : "=l"(r) : "f"(x)); return r;
}
__device__ __forceinline__ void ffma2(ull& d, ull a, ull b) {
    asm("fma.rn.f32x2 %0, %1, %2, %3;" : "=l"(d) : "l"(a), "l"(b), "l"(d));
}
__device__ __forceinline__ float2 unpk(ull v) {
    float2 f; asm("mov.b64 {%0, %1}, %2;" : "=f"(f.x), "=f"(f.y) : "l"(v)); return f;
}
__device__ __forceinline__ unsigned cvt_tf32(float x) {
    unsigned r; asm("cvt.rna.tf32.f32 %0, %1;" : "=r"(r) : "f"(x)); return r;
}
__device__ __forceinline__ void mma_tf32(float* c,
    unsigned a0, unsigned a1, unsigned a2, unsigned a3,
    unsigned b0, unsigned b1) {
    asm volatile(
        "mma.sync.aligned.m16n8k8.row.col.f32.tf32.tf32.f32 "
        "{%0,%1,%2,%3}, {%4,%5,%6,%7}, {%8,%9}, {%0,%1,%2,%3};"
        : "+f"(c[0]), "+f"(c[1]), "+f"(c[2]), "+f"(c[3])
        : "r"(a0), "r"(a1), "r"(a2), "r"(a3), "r"(b0), "r"(b1));
}

__device__ float g_qb[BH * NBLK * Dd];
__device__ float g_kb[BH * NBLK * Dd];
__device__ int   g_lut[BH * NBLK * TSEL];
__device__ float g_kv[(size_t)BH * NBLK * Dd * Dd];
__device__ float g_z[BH * NBLK * Dd];
__device__ float g_kvtot[BH * Dd * Dd];
__device__ float g_ztot[BH * Dd];

#define GSTEP(Abase, Bbase, ACC)                                        \
    {                                                                   \
        float4 af = *(const float4*)(Abase);                            \
        ulonglong2 bp = *(const ulonglong2*)(Bbase);                    \
        ull a0 = dup2(af.x), a1 = dup2(af.y), a2 = dup2(af.z), a3 = dup2(af.w); \
        ffma2(ACC[0], a0, bp.x); ffma2(ACC[1], a0, bp.y);               \
        ffma2(ACC[2], a1, bp.x); ffma2(ACC[3], a1, bp.y);               \
        ffma2(ACC[4], a2, bp.x); ffma2(ACC[5], a2, bp.y);               \
        ffma2(ACC[6], a3, bp.x); ffma2(ACC[7], a3, bp.y);               \
    }

// ---------------------------------------------------------------------------
// q block means only (k means fused into k_kvz). grid 512, block 256.
// ---------------------------------------------------------------------------
__global__ void k_qmean(const float* __restrict__ q) {
    int blk = blockIdx.x * 4 + (threadIdx.x >> 6);
    int d = threadIdx.x & 63;
    const float* base = q + (size_t)blk * 64 * Dd + d;
    float s = 0.f;
#pragma unroll
    for (int r = 0; r < 64; r++) s += base[r * Dd];
    g_qb[blk * Dd + d] = s * (1.f / 64.f);
}

// ---------------------------------------------------------------------------
__global__ void k_topk() {
    int bh = blockIdx.x >> 6, qb = blockIdx.x & 63;
    __shared__ float qrow[Dd];
    __shared__ float sc[NBLK];
    int t = threadIdx.x;
    qrow[t] = g_qb[(bh * NBLK + qb) * Dd + t];
    __syncthreads();
    const float* kb = g_kb + (bh * NBLK + t) * Dd;
    float acc = 0.f;
#pragma unroll
    for (int d = 0; d < Dd; d++) acc += qrow[d] * kb[d];
    sc[t] = acc * SCALE;
    __syncthreads();
    if (t == 0) {
        for (int s = 0; s < TSEL; s++) {
            float best = -3.4e38f; int bi = 0;
            for (int j = 0; j < NBLK; j++)
                if (sc[j] > best) { best = sc[j]; bi = j; }
            g_lut[(bh * NBLK + qb) * TSEL + s] = bi;
            sc[bi] = -3.4e38f;
        }
    }
}

// ---------------------------------------------------------------------------
// K3: kv = phi(k)^T v, z = sum phi(k), and fused k block means.
// ---------------------------------------------------------------------------
__global__ void __launch_bounds__(256) k_kvz(const float* __restrict__ k,
                                             const float* __restrict__ v) {
    __shared__ float ck[64 * P68];
    __shared__ float vs[64 * P68];
    int tid = threadIdx.x;
    int bh = blockIdx.x >> 6, kb = blockIdx.x & 63;
    size_t goff = ((size_t)bh * Ll + kb * 64) * Dd;
    int vm = tid >> 4, ve = (tid & 15) * 4;
#pragma unroll
    for (int p = 0; p < 4; p++) {
        int m = vm + p * 16;
        *(float4*)&ck[m * P68 + ve] = *(const float4*)&k[goff + (size_t)m * 64 + ve];
        *(float4*)&vs[m * P68 + ve] = *(const float4*)&v[goff + (size_t)m * 64 + ve];
    }
    __syncthreads();
    // fused k block mean (raw k, before in-place softmax)
    if (tid < 64) {
        float s = 0.f;
#pragma unroll
        for (int m = 0; m < 64; m++) s += ck[m * P68 + tid];
        g_kb[(bh * NBLK + kb) * Dd + tid] = s * (1.f / 64.f);
    }
    __syncthreads();
    int warp = tid >> 5, lane = tid & 31;
    for (int r = warp; r < 64; r += 8) {
        float e0 = __expf(ck[r * P68 + lane]);
        float e1 = __expf(ck[r * P68 + lane + 32]);
        float s = e0 + e1;
#pragma unroll
        for (int o = 16; o; o >>= 1) s += __shfl_xor_sync(~0u, s, o);
        float inv = 1.f / s;
        ck[r * P68 + lane] = e0 * inv;
        ck[r * P68 + lane + 32] = e1 * inv;
    }
    __syncthreads();
    int tr = tid >> 4, tc = tid & 15;
    ull acc2[8];
#pragma unroll
    for (int i = 0; i < 8; i++) acc2[i] = 0ull;
#pragma unroll 16
    for (int m = 0; m < 64; m++)
        GSTEP(&ck[m * P68 + tr * 4], &vs[m * P68 + tc * 4], acc2);
    float* kvout = g_kv + ((size_t)(bh * NBLK + kb)) * Dd * Dd;
#pragma unroll
    for (int i = 0; i < 4; i++) {
        float2 c01 = unpk(acc2[i * 2]), c23 = unpk(acc2[i * 2 + 1]);
        *(float4*)&kvout[(tr * 4 + i) * Dd + tc * 4] =
            make_float4(c01.x, c01.y, c23.x, c23.y);
    }
    if (tid < 64) {
        float s = 0.f;
#pragma unroll
        for (int m = 0; m < 64; m++) s += ck[m * P68 + tid];
        g_z[(bh * NBLK + kb) * Dd + tid] = s;
    }
}

// ---------------------------------------------------------------------------
// K4: totals (R10 config: grid (BH,16), block 256)
// ---------------------------------------------------------------------------
__global__ void k_totals() {
    int bh = blockIdx.x, tid = threadIdx.x;
    int e = blockIdx.y * 256 + tid;
    const float* p = g_kv + (size_t)bh * NBLK * Dd * Dd + e;
    float s = 0.f;
#pragma unroll 8
    for (int kb = 0; kb < NBLK; kb++) s += p[(size_t)kb * Dd * Dd];
    g_kvtot[bh * Dd * Dd + e] = s;
    if (blockIdx.y == 0 && tid < Dd) {
        const float* pz = g_z + bh * NBLK * Dd + tid;
        float sz = 0.f;
#pragma unroll 8
        for (int kb = 0; kb < NBLK; kb++) sz += pz[kb * Dd];
        g_ztot[bh * Dd + tid] = sz;
    }
}

// ---------------------------------------------------------------------------
// K5: tf32 mma main kernel — R10 version, UNTOUCHED.
// ---------------------------------------------------------------------------
__global__ void __launch_bounds__(256, 2) k_main(
    const float* __restrict__ q, const float* __restrict__ k,
    const float* __restrict__ v, const float* __restrict__ W,
    const float* __restrict__ b, float* __restrict__ out)
{
    extern __shared__ float sm[];
    float* Qb  = sm;            // raw fp32 Q; later c_q
    float* Pb  = sm + 4352;     // tf32 P; later tf32 o_l
    float* Kb0 = sm + 8704;     // tf32 K (buf0); later tf32 kvns^T
    float* Kb1 = sm + 13056;    // tf32 K (buf1)
    float* VT0 = sm + 17408;    // tf32 V^T (buf0); later tf32 W
    float* VT1 = sm + 21760;    // tf32 V^T (buf1)
    float* zns = sm + 26112;
    float* bl  = sm + 26176;
    float* den = sm + 26240;
    __shared__ int lut[8];

    int tid = threadIdx.x;
    int bh = blockIdx.x >> 6, qb = blockIdx.x & 63;
    size_t qoff = ((size_t)bh * Ll + qb * 64) * Dd;

    if (tid < TSEL) lut[tid] = g_lut[(bh * NBLK + qb) * TSEL + tid];
    if (tid < 64) bl[tid] = b[tid];

    // stage Q raw (coalesced float4)
#pragma unroll
    for (int i = 0; i < 4; i++) {
        int idx = tid + 256 * i;
        int row = idx >> 4, c4 = (idx & 15) * 4;
        *(float4*)&Qb[row * P68 + c4] = *(const float4*)&q[qoff + (size_t)row * 64 + c4];
    }
    __syncthreads();   // lut visible

    // stage K/V block 0 (all threads)
    {
        size_t ko = ((size_t)bh * Ll + (size_t)lut[0] * 64) * Dd;
        unsigned* KU = (unsigned*)Kb0;
#pragma unroll
        for (int i = 0; i < 4; i++) {
            int idx = tid + 256 * i;
            int row = idx >> 4, c4 = (idx & 15) * 4;
            float4 f = *(const float4*)&k[ko + (size_t)row * 64 + c4];
            *(uint4*)&KU[row * P68 + c4] =
                make_uint4(cvt_tf32(f.x), cvt_tf32(f.y), cvt_tf32(f.z), cvt_tf32(f.w));
        }
        unsigned* VU = (unsigned*)VT0;
        int dd = tid & 63, h16 = (tid >> 6) * 16;
#pragma unroll
        for (int r = 0; r < 16; r++)
            VU[dd * P68 + h16 + r] = cvt_tf32(v[ko + (size_t)(h16 + r) * 64 + dd]);
    }
    __syncthreads();

    int wid = tid >> 5, lane = tid & 31;
    int grp = lane >> 2, tig = lane & 3;
    int r0 = (wid & 3) * 16;
    unsigned* PbU = (unsigned*)Pb;

    float OS[8][4];
#pragma unroll
    for (int i = 0; i < 8; i++)
#pragma unroll
        for (int j = 0; j < 4; j++) OS[i][j] = 0.f;
    float lp0 = 0.f, lp1 = 0.f;

    for (int t = 0; t < TSEL; t++) {
        const unsigned* KU = (const unsigned*)((t & 1) ? Kb1 : Kb0);
        const unsigned* VU = (const unsigned*)((t & 1) ? VT1 : VT0);
        if (wid < 4) {
            // ---- S = Q K^T ----
            float Sc[8][4];
#pragma unroll
            for (int i = 0; i < 8; i++)
#pragma unroll
                for (int j = 0; j < 4; j++) Sc[i][j] = 0.f;
#pragma unroll
            for (int k8 = 0; k8 < 8; k8++) {
                int k0 = 8 * k8;
                unsigned a0 = cvt_tf32(Qb[(r0 + grp) * P68 + k0 + tig]);
                unsigned a1 = cvt_tf32(Qb[(r0 + grp + 8) * P68 + k0 + tig]);
                unsigned a2 = cvt_tf32(Qb[(r0 + grp) * P68 + k0 + tig + 4]);
                unsigned a3 = cvt_tf32(Qb[(r0 + grp + 8) * P68 + k0 + tig + 4]);
#pragma unroll
                for (int nt = 0; nt < 8; nt++) {
                    unsigned b0 = KU[(8 * nt + grp) * P68 + k0 + tig];
                    unsigned b1 = KU[(8 * nt + grp) * P68 + k0 + tig + 4];
                    mma_tf32(Sc[nt], a0, a1, a2, a3, b0, b1);
                }
            }
            // ---- exp (no max), write tf32 P, accumulate row sums ----
#pragma unroll
            for (int nt = 0; nt < 8; nt++) {
                float e0 = __expf(Sc[nt][0] * SCALE), e1 = __expf(Sc[nt][1] * SCALE);
                float e2 = __expf(Sc[nt][2] * SCALE), e3 = __expf(Sc[nt][3] * SCALE);
                lp0 += e0 + e1; lp1 += e2 + e3;
                *(uint2*)&PbU[(r0 + grp) * P68 + 8 * nt + 2 * tig] =
                    make_uint2(cvt_tf32(e0), cvt_tf32(e1));
                *(uint2*)&PbU[(r0 + grp + 8) * P68 + 8 * nt + 2 * tig] =
                    make_uint2(cvt_tf32(e2), cvt_tf32(e3));
            }
            __syncwarp();
            // ---- o_s += P V ----
#pragma unroll
            for (int k8 = 0; k8 < 8; k8++) {
                int m0 = 8 * k8;
                unsigned a0 = PbU[(r0 + grp) * P68 + m0 + tig];
                unsigned a1 = PbU[(r0 + grp + 8) * P68 + m0 + tig];
                unsigned a2 = PbU[(r0 + grp) * P68 + m0 + tig + 4];
                unsigned a3 = PbU[(r0 + grp + 8) * P68 + m0 + tig + 4];
#pragma unroll
                for (int nt = 0; nt < 8; nt++) {
                    unsigned b0 = VU[(8 * nt + grp) * P68 + m0 + tig];
                    unsigned b1 = VU[(8 * nt + grp) * P68 + m0 + tig + 4];
                    mma_tf32(OS[nt], a0, a1, a2, a3, b0, b1);
                }
            }
        } else if (t + 1 < TSEL) {
            // ---- producers: stage K/V for t+1 into the other buffer ----
            int ptid = tid - 128;
            size_t ko = ((size_t)bh * Ll + (size_t)lut[t + 1] * 64) * Dd;
            unsigned* KU2 = (unsigned*)((t & 1) ? Kb0 : Kb1);
            unsigned* VU2 = (unsigned*)((t & 1) ? VT0 : VT1);
#pragma unroll
            for (int i = 0; i < 8; i++) {
                int idx = ptid + 128 * i;
                int row = idx >> 4, c4 = (idx & 15) * 4;
                float4 f = *(const float4*)&k[ko + (size_t)row * 64 + c4];
                *(uint4*)&KU2[row * P68 + c4] =
                    make_uint4(cvt_tf32(f.x), cvt_tf32(f.y), cvt_tf32(f.z), cvt_tf32(f.w));
            }
            int dd = ptid & 63, h32 = (ptid >> 6) * 32;
#pragma unroll
            for (int r = 0; r < 32; r++)
                VU2[dd * P68 + h32 + r] = cvt_tf32(v[ko + (size_t)(h32 + r) * 64 + dd]);
        }
        __syncthreads();
    }

    // row sums of exp (lanes 4g..4g+3 share rows r0+grp / r0+grp+8)
    float l0 = lp0, l1 = lp1;
    l0 += __shfl_xor_sync(~0u, l0, 1); l0 += __shfl_xor_sync(~0u, l0, 2);
    l1 += __shfl_xor_sync(~0u, l1, 1); l1 += __shfl_xor_sync(~0u, l1, 2);

    // ---- c_q = softmax(q) over D (no max; thread per row, in place) ----
    if (tid < 64) {
        float s = 0.f;
#pragma unroll 8
        for (int d = 0; d < 64; d++) {
            float e = __expf(Qb[tid * P68 + d]);
            Qb[tid * P68 + d] = e; s += e;
        }
        float inv = 1.f / s;
#pragma unroll 8
        for (int d = 0; d < 64; d++) Qb[tid * P68 + d] *= inv;
    }

    // ---- kvns^T into Kb0 (tf32), z_ns; stage W into VT0 (tf32) ----
    {
        unsigned* NU = (unsigned*)Kb0;
        int d0 = tid >> 2, e0 = (tid & 3) * 16;
        const float* kvt = g_kvtot + bh * Dd * Dd;
#pragma unroll
        for (int p = 0; p < 4; p++) {
            float4 s = *(const float4*)&kvt[d0 * 64 + e0 + 4 * p];
#pragma unroll
            for (int t = 0; t < TSEL; t++) {
                const float4 x = *(const float4*)
                    &g_kv[((size_t)(bh * NBLK + lut[t])) * Dd * Dd + d0 * 64 + e0 + 4 * p];
                s.x -= x.x; s.y -= x.y; s.z -= x.z; s.w -= x.w;
            }
            NU[(e0 + 4 * p + 0) * P68 + d0] = cvt_tf32(s.x);
            NU[(e0 + 4 * p + 1) * P68 + d0] = cvt_tf32(s.y);
            NU[(e0 + 4 * p + 2) * P68 + d0] = cvt_tf32(s.z);
            NU[(e0 + 4 * p + 3) * P68 + d0] = cvt_tf32(s.w);
        }
        if (tid < 64) {
            float s = g_ztot[bh * Dd + tid];
#pragma unroll
            for (int t = 0; t < TSEL; t++) s -= g_z[(bh * NBLK + lut[t]) * Dd + tid];
            zns[tid] = s;
        }
        unsigned* WU = (unsigned*)VT0;
#pragma unroll
        for (int i = 0; i < 4; i++) {
            int idx = tid + 256 * i;
            int row = idx >> 4, c4 = (idx & 15) * 4;
            float4 f = *(const float4*)&W[row * 64 + c4];
            *(uint4*)&WU[row * P68 + c4] =
                make_uint4(cvt_tf32(f.x), cvt_tf32(f.y), cvt_tf32(f.z), cvt_tf32(f.w));
        }
    }
    __syncthreads();

    // ---- den ----
    if (tid < 64) {
        float s = 0.f;
#pragma unroll 8
        for (int d = 0; d < 64; d++) s += Qb[tid * P68 + d] * zns[d];
        den[tid] = s;
    }
    __syncthreads();

    if (wid < 4) {
        const unsigned* NU = (const unsigned*)Kb0;
        const unsigned* WU = (const unsigned*)VT0;
        // ---- num = c_q kv_ns ----
        float OL[8][4];
#pragma unroll
        for (int i = 0; i < 8; i++)
#pragma unroll
            for (int j = 0; j < 4; j++) OL[i][j] = 0.f;
#pragma unroll
        for (int k8 = 0; k8 < 8; k8++) {
            int k0 = 8 * k8;
            unsigned a0 = cvt_tf32(Qb[(r0 + grp) * P68 + k0 + tig]);
            unsigned a1 = cvt_tf32(Qb[(r0 + grp + 8) * P68 + k0 + tig]);
            unsigned a2 = cvt_tf32(Qb[(r0 + grp) * P68 + k0 + tig + 4]);
            unsigned a3 = cvt_tf32(Qb[(r0 + grp + 8) * P68 + k0 + tig + 4]);
#pragma unroll
            for (int nt = 0; nt < 8; nt++) {
                unsigned b0 = NU[(8 * nt + grp) * P68 + k0 + tig];
                unsigned b1 = NU[(8 * nt + grp) * P68 + k0 + tig + 4];
                mma_tf32(OL[nt], a0, a1, a2, a3, b0, b1);
            }
        }
        float i0 = 1.f / (den[r0 + grp] + 1e-6f);
        float i1 = 1.f / (den[r0 + grp + 8] + 1e-6f);
#pragma unroll
        for (int nt = 0; nt < 8; nt++) {
            *(uint2*)&PbU[(r0 + grp) * P68 + 8 * nt + 2 * tig] =
                make_uint2(cvt_tf32(OL[nt][0] * i0), cvt_tf32(OL[nt][1] * i0));
            *(uint2*)&PbU[(r0 + grp + 8) * P68 + 8 * nt + 2 * tig] =
                make_uint2(cvt_tf32(OL[nt][2] * i1), cvt_tf32(OL[nt][3] * i1));
        }
        __syncwarp();
        // ---- proj = o_l W^T ----
        float PR[8][4];
#pragma unroll
        for (int i = 0; i < 8; i++)
#pragma unroll
            for (int j = 0; j < 4; j++) PR[i][j] = 0.f;
#pragma unroll
        for (int k8 = 0; k8 < 8; k8++) {
            int k0 = 8 * k8;
            unsigned a0 = PbU[(r0 + grp) * P68 + k0 + tig];
            unsigned a1 = PbU[(r0 + grp + 8) * P68 + k0 + tig];
            unsigned a2 = PbU[(r0 + grp) * P68 + k0 + tig + 4];
            unsigned a3 = PbU[(r0 + grp + 8) * P68 + k0 + tig + 4];
#pragma unroll
            for (int nt = 0; nt < 8; nt++) {
                unsigned b0 = WU[(8 * nt + grp) * P68 + k0 + tig];
                unsigned b1 = WU[(8 * nt + grp) * P68 + k0 + tig + 4];
                mma_tf32(PR[nt], a0, a1, a2, a3, b0, b1);
            }
        }
        // ---- write out = o_s/l + proj + b ----
        float inv0 = 1.f / l0, inv1 = 1.f / l1;
#pragma unroll
        for (int nt = 0; nt < 8; nt++) {
            int c = 8 * nt + 2 * tig;
            float2 bv = *(float2*)&bl[c];
            *(float2*)&out[qoff + (size_t)(r0 + grp) * 64 + c] =
                make_float2(OS[nt][0] * inv0 + PR[nt][0] + bv.x,
                            OS[nt][1] * inv0 + PR[nt][1] + bv.y);
            *(float2*)&out[qoff + (size_t)(r0 + grp + 8) * 64 + c] =
                make_float2(OS[nt][2] * inv1 + PR[nt][2] + bv.x,
                            OS[nt][3] * inv1 + PR[nt][3] + bv.y);
        }
    }
}

// ---------------------------------------------------------------------------
extern "C" void kernel_launch(void* const* d_in, const int* in_sizes, int n_in,
                              void* d_out, int out_size) {
    const float* q = (const float*)d_in[0];
    const float* k = (const float*)d_in[1];
    const float* v = (const float*)d_in[2];
    const float* W = (const float*)d_in[3];
    const float* b = (const float*)d_in[4];
    float* out = (float*)d_out;

    int smem_main = 26304 * (int)sizeof(float);
    cudaFuncSetAttribute(k_main, cudaFuncAttributeMaxDynamicSharedMemorySize, smem_main);

    k_qmean<<<512, 256>>>(q);
    k_kvz<<<BH * NBLK, 256>>>(k, v);
    k_topk<<<BH * NBLK, 64>>>();
    k_totals<<<dim3(BH, 16), 256>>>();
    k_main<<<BH * NBLK, 256, smem_main>>>(q, k, v, W, b, out);
}